// round 5
// baseline (speedup 1.0000x reference)
#include <cuda_runtime.h>
#include <math.h>

#define TWO_N 8192
#define NHALF 4096
#define DIMS 256
#define BM 128
#define BN 128
#define BK 32
#define BMP 132
#define NBLK 64                          // 8192 / 128
#define NTILES (NBLK * (NBLK + 1) / 2)   // 2080 upper-triangular tiles

// ---- scratch (no allocations allowed) ----
__device__ float g_norms[TWO_N];
__device__ float g_partial[NBLK * TWO_N];      // [colBlock][row] partial row sums, 2 MB
__device__ float g_rows[TWO_N];
__device__ float g_ap[NHALF];
__device__ unsigned int g_mbits[TWO_N * 256]; // packed mask bits, 8 MB
__device__ int g_mask_log2sz;                  // 0: u8, 1: 16-bit, 2: 32-bit elements

// ---------------------------------------------------------------------------
// 0a) detect mask element size from the OR of the first 8192 32-bit words.
//     bool data ORs to exactly: 0x01010101 (u8), 0x00010001/0x3F803F80 (16b),
//     0x00000001/0x3F800000 (32b int/float).
// ---------------------------------------------------------------------------
__global__ __launch_bounds__(256) void detect_kernel(const unsigned int* __restrict__ mask_raw) {
    __shared__ unsigned int sor[256];
    unsigned int v = 0;
#pragma unroll
    for (int c = 0; c < 32; c++) v |= mask_raw[threadIdx.x + 256 * c];
    sor[threadIdx.x] = v;
    __syncthreads();
    for (int o = 128; o > 0; o >>= 1) {
        if (threadIdx.x < o) sor[threadIdx.x] |= sor[threadIdx.x + o];
        __syncthreads();
    }
    if (threadIdx.x == 0) {
        unsigned int orv = sor[0];
        int m = 2;                                            // default: 32-bit elements
        if (orv == 0x01010101u) m = 0;                        // uint8 bools
        else if (orv == 0x00010001u || orv == 0x3F803F80u) m = 1;  // 16-bit bools
        g_mask_log2sz = m;
    }
}

// ---------------------------------------------------------------------------
// 0b) pack mask to bits (one thread per output uint32 = 32 columns).
//     Nonzero-element test works for int 1 and float 1.0 alike.
// ---------------------------------------------------------------------------
__global__ __launch_bounds__(256) void pack_kernel(const void* __restrict__ mask_raw) {
    int w = blockIdx.x * blockDim.x + threadIdx.x;
    if (w >= TWO_N * 256) return;
    unsigned int bits = 0;
    int mode = g_mask_log2sz;
    if (mode == 2) {                 // 32-bit elements
        const uint4* p = (const uint4*)((const unsigned int*)mask_raw + (size_t)w * 32);
#pragma unroll
        for (int q = 0; q < 8; q++) {
            uint4 v = p[q];
            bits |= (v.x ? 1u : 0u) << (4 * q + 0);
            bits |= (v.y ? 1u : 0u) << (4 * q + 1);
            bits |= (v.z ? 1u : 0u) << (4 * q + 2);
            bits |= (v.w ? 1u : 0u) << (4 * q + 3);
        }
    } else if (mode == 1) {          // 16-bit elements
        const uint4* p = (const uint4*)((const unsigned short*)mask_raw + (size_t)w * 32);
#pragma unroll
        for (int q = 0; q < 4; q++) {
            uint4 v = p[q];
            unsigned int words[4] = {v.x, v.y, v.z, v.w};
#pragma unroll
            for (int t = 0; t < 4; t++) {
                bits |= ((words[t] & 0x0000FFFFu) ? 1u : 0u) << (8 * q + 2 * t + 0);
                bits |= ((words[t] & 0xFFFF0000u) ? 1u : 0u) << (8 * q + 2 * t + 1);
            }
        }
    } else {                         // uint8 elements
        const uint4* p = (const uint4*)((const unsigned char*)mask_raw + (size_t)w * 32);
#pragma unroll
        for (int q = 0; q < 2; q++) {
            uint4 v = p[q];
            unsigned int words[4] = {v.x, v.y, v.z, v.w};
#pragma unroll
            for (int t = 0; t < 4; t++)
#pragma unroll
                for (int b = 0; b < 4; b++)
                    bits |= (((words[t] >> (8 * b)) & 0xffu) ? 1u : 0u) << (16 * q + 4 * t + b);
        }
    }
    g_mbits[w] = bits;
}

// ---------------------------------------------------------------------------
// 1) squared row norms (one warp per row)
// ---------------------------------------------------------------------------
__global__ __launch_bounds__(256) void norms_kernel(const float* __restrict__ emb) {
    int warp = (blockIdx.x * blockDim.x + threadIdx.x) >> 5;
    int lane = threadIdx.x & 31;
    if (warp >= TWO_N) return;
    const float4* p = (const float4*)(emb + (size_t)warp * DIMS);
    float s = 0.f;
#pragma unroll
    for (int c = 0; c < 2; c++) {
        float4 v = p[lane + 32 * c];
        s += v.x * v.x + v.y * v.y + v.z * v.z + v.w * v.w;
    }
#pragma unroll
    for (int o = 16; o > 0; o >>= 1) s += __shfl_down_sync(0xffffffffu, s, o);
    if (lane == 0) g_norms[warp] = s;
}

// ---------------------------------------------------------------------------
// 2) upper-triangular fused Gram + distance + masked exp, symmetric reuse.
//    2080 blocks, 256 threads, 8x8 outputs/thread, f32x2 packed FMA.
// ---------------------------------------------------------------------------
__global__ __launch_bounds__(256, 2) void pair_kernel(const float* __restrict__ emb) {
    __shared__ float As[BK][BMP];
    __shared__ float Bs[BK][BMP];
    __shared__ float rowpart[BM][17];
    __shared__ float colpart[BN][17];

    // decode linear tile id -> (by, bx) with bx >= by
    int t = blockIdx.x;
    int by = (int)((2 * NBLK + 1 - sqrtf((float)((2 * NBLK + 1) * (2 * NBLK + 1) - 8 * t))) * 0.5f);
    while ((by + 1) * NBLK - ((by + 1) * by) / 2 <= t) by++;    // fixup sqrt rounding
    while (by * NBLK - (by * (by - 1)) / 2 > t) by--;
    int bx = by + (t - (by * NBLK - (by * (by - 1)) / 2));
    const bool diag = (bx == by);

    const int tid = threadIdx.x;
    const int tx = tid & 15;
    const int ty = tid >> 4;
    const int rowBase = by * BM, colBase = bx * BN;

    unsigned long long acc[8][4];
#pragma unroll
    for (int i = 0; i < 8; i++)
#pragma unroll
        for (int j = 0; j < 4; j++) acc[i][j] = 0ull;

    for (int k0 = 0; k0 < DIMS; k0 += BK) {
#pragma unroll
        for (int c = 0; c < 4; c++) {
            int f4  = tid + c * 256;
            int row = f4 >> 3;
            int k4  = (f4 & 7) << 2;
            float4 va = *(const float4*)(emb + (size_t)(rowBase + row) * DIMS + k0 + k4);
            As[k4 + 0][row] = va.x; As[k4 + 1][row] = va.y;
            As[k4 + 2][row] = va.z; As[k4 + 3][row] = va.w;
            float4 vb = *(const float4*)(emb + (size_t)(colBase + row) * DIMS + k0 + k4);
            Bs[k4 + 0][row] = vb.x; Bs[k4 + 1][row] = vb.y;
            Bs[k4 + 2][row] = vb.z; Bs[k4 + 3][row] = vb.w;
        }
        __syncthreads();
#pragma unroll
        for (int kk = 0; kk < BK; kk++) {
            float4 a0 = *(const float4*)&As[kk][ty * 8];
            float4 a1 = *(const float4*)&As[kk][ty * 8 + 4];
            ulonglong2 bq0 = *(const ulonglong2*)&Bs[kk][tx * 8];
            ulonglong2 bq1 = *(const ulonglong2*)&Bs[kk][tx * 8 + 4];
            unsigned long long bp[4] = {bq0.x, bq0.y, bq1.x, bq1.y};
            float av[8] = {a0.x, a0.y, a0.z, a0.w, a1.x, a1.y, a1.z, a1.w};
            unsigned long long a2[8];
#pragma unroll
            for (int i = 0; i < 8; i++)
                asm("mov.b64 %0, {%1, %1};" : "=l"(a2[i]) : "r"(__float_as_int(av[i])));
#pragma unroll
            for (int i = 0; i < 8; i++)
#pragma unroll
                for (int j = 0; j < 4; j++)
                    asm("fma.rn.f32x2 %0, %1, %2, %0;"
                        : "+l"(acc[i][j]) : "l"(a2[i]), "l"(bp[j]));
        }
        __syncthreads();
    }

    // ---- epilogue ----
    float4 nc0 = *(const float4*)(g_norms + colBase + tx * 8);
    float4 nc1 = *(const float4*)(g_norms + colBase + tx * 8 + 4);
    float ncol[8] = {nc0.x, nc0.y, nc0.z, nc0.w, nc1.x, nc1.y, nc1.z, nc1.w};
    const unsigned char* mb8 = (const unsigned char*)g_mbits;

    // transposed mask bytes: mask[c][rowBase+ty*8 .. +7] for my 8 columns c
    unsigned int mbt[8];
#pragma unroll
    for (int j = 0; j < 8; j++) {
        int c = colBase + tx * 8 + j;
        mbt[j] = diag ? 0u : mb8[(size_t)c * 1024 + (rowBase >> 3) + ty];
    }

    float strans[8] = {0.f, 0.f, 0.f, 0.f, 0.f, 0.f, 0.f, 0.f};
#pragma unroll
    for (int i = 0; i < 8; i++) {
        int r = rowBase + ty * 8 + i;
        float nr = __ldg(g_norms + r);
        unsigned int mb = mb8[(size_t)r * 1024 + (colBase >> 3) + tx];
        const float* dots = (const float*)acc[i];
        float s = 0.f;
#pragma unroll
        for (int j = 0; j < 8; j++) {
            float sq = nr + ncol[j] - 2.f * dots[j];
            sq = fmaxf(sq, 0.f);
            float d = sqrtf(sq + 1e-12f);
            int c = colBase + tx * 8 + j;
            if (c - r == NHALF) g_ap[r] = d;           // bx = by+32, always in triangle
            float e = __expf(0.5f - d);
            if ((mb >> j) & 1u) s += e;                 // direct: rowsum[r], col c
            if ((mbt[j] >> i) & 1u) strans[j] += e;     // mirror: rowsum[c], col r
        }
        rowpart[ty * 8 + i][tx] = s;
    }
#pragma unroll
    for (int j = 0; j < 8; j++) colpart[tx * 8 + j][ty] = strans[j];
    __syncthreads();

    if (tid < BM) {
        float s = 0.f;
#pragma unroll
        for (int k = 0; k < 16; k++) s += rowpart[tid][k];
        g_partial[(size_t)bx * TWO_N + rowBase + tid] = s;       // slot (p=bx, rows of by)
        if (!diag) {
            float sc = 0.f;
#pragma unroll
            for (int k = 0; k < 16; k++) sc += colpart[tid][k];
            g_partial[(size_t)by * TWO_N + colBase + tid] = sc;  // slot (p=by, rows of bx)
        }
    }
}

// ---------------------------------------------------------------------------
// 3) reduce partial row sums over the 64 column blocks
// ---------------------------------------------------------------------------
__global__ __launch_bounds__(256) void rowsum_kernel() {
    int r = blockIdx.x * blockDim.x + threadIdx.x;
    if (r >= TWO_N) return;
    float s = 0.f;
#pragma unroll
    for (int b = 0; b < NBLK; b++) s += g_partial[(size_t)b * TWO_N + r];
    g_rows[r] = s;
}

// ---------------------------------------------------------------------------
// 4) final loss (single block; deterministic)
// ---------------------------------------------------------------------------
__global__ __launch_bounds__(1024) void loss_kernel(float* __restrict__ out) {
    __shared__ float ssum[32];
    __shared__ int scnt[32];
    float s = 0.f;
    int cnt = 0;
    for (int i = threadIdx.x; i < NHALF; i += 1024) {
        float jv = logf(g_rows[i] + g_rows[i + NHALF]) + g_ap[i];
        if (!isnan(jv)) {
            float mj = fmaxf(jv, 0.f);
            s += mj * mj;
            cnt++;
        }
    }
    int lane = threadIdx.x & 31, w = threadIdx.x >> 5;
#pragma unroll
    for (int o = 16; o > 0; o >>= 1) {
        s += __shfl_down_sync(0xffffffffu, s, o);
        cnt += __shfl_down_sync(0xffffffffu, cnt, o);
    }
    if (lane == 0) { ssum[w] = s; scnt[w] = cnt; }
    __syncthreads();
    if (w == 0) {
        s = ssum[lane];
        cnt = scnt[lane];
#pragma unroll
        for (int o = 16; o > 0; o >>= 1) {
            s += __shfl_down_sync(0xffffffffu, s, o);
            cnt += __shfl_down_sync(0xffffffffu, cnt, o);
        }
        if (lane == 0) out[0] = s / fmaxf((float)cnt, 1.f) * 0.5f;
    }
}

// ---------------------------------------------------------------------------
extern "C" void kernel_launch(void* const* d_in, const int* in_sizes, int n_in,
                              void* d_out, int out_size) {
    const float* emb = (const float*)d_in[0];
    const void* mask = d_in[1];
    float* out = (float*)d_out;

    detect_kernel<<<1, 256>>>((const unsigned int*)mask);
    pack_kernel<<<TWO_N * 256 / 256, 256>>>(mask);
    norms_kernel<<<TWO_N / 8, 256>>>(emb);
    pair_kernel<<<NTILES, 256>>>(emb);
    rowsum_kernel<<<TWO_N / 256, 256>>>();
    loss_kernel<<<1, 1024>>>(out);
}

// round 14
// speedup vs baseline: 1.0654x; 1.0654x over previous
#include <cuda_runtime.h>
#include <math.h>

#define TWO_N 8192
#define NHALF 4096
#define DIMS 256
#define BM 128
#define BN 128
#define BK 32
#define BMP 132
#define NBLK 64                          // 8192 / 128
#define NTILES (NBLK * (NBLK + 1) / 2)   // 2080 upper-triangular tiles

// ---- scratch (no allocations allowed) ----
__device__ float g_norms[TWO_N];
__device__ float g_partial[NBLK * TWO_N];      // [colBlock][row] partial row sums, 2 MB
__device__ float g_rows[TWO_N];
__device__ float g_ap[NHALF];
__device__ unsigned int g_mbits[TWO_N * 256]; // packed mask bits, 8 MB
__device__ int g_mask_log2sz;                  // 0: u8, 1: 16-bit, 2: 32-bit elements

// ---------------------------------------------------------------------------
// 0a) detect mask element size from the OR of the first 8192 32-bit words.
// ---------------------------------------------------------------------------
__global__ __launch_bounds__(256) void detect_kernel(const unsigned int* __restrict__ mask_raw) {
    __shared__ unsigned int sor[256];
    unsigned int v = 0;
#pragma unroll
    for (int c = 0; c < 32; c++) v |= mask_raw[threadIdx.x + 256 * c];
    sor[threadIdx.x] = v;
    __syncthreads();
    for (int o = 128; o > 0; o >>= 1) {
        if (threadIdx.x < o) sor[threadIdx.x] |= sor[threadIdx.x + o];
        __syncthreads();
    }
    if (threadIdx.x == 0) {
        unsigned int orv = sor[0];
        int m = 2;                                            // default: 32-bit elements
        if (orv == 0x01010101u) m = 0;                        // uint8 bools
        else if (orv == 0x00010001u || orv == 0x3F803F80u) m = 1;  // 16-bit bools
        g_mask_log2sz = m;
    }
}

// ---------------------------------------------------------------------------
// 0b) pack mask to bits (one thread per output uint32 = 32 columns)
// ---------------------------------------------------------------------------
__global__ __launch_bounds__(256) void pack_kernel(const void* __restrict__ mask_raw) {
    int w = blockIdx.x * blockDim.x + threadIdx.x;
    if (w >= TWO_N * 256) return;
    unsigned int bits = 0;
    int mode = g_mask_log2sz;
    if (mode == 2) {                 // 32-bit elements
        const uint4* p = (const uint4*)((const unsigned int*)mask_raw + (size_t)w * 32);
#pragma unroll
        for (int q = 0; q < 8; q++) {
            uint4 v = p[q];
            bits |= (v.x ? 1u : 0u) << (4 * q + 0);
            bits |= (v.y ? 1u : 0u) << (4 * q + 1);
            bits |= (v.z ? 1u : 0u) << (4 * q + 2);
            bits |= (v.w ? 1u : 0u) << (4 * q + 3);
        }
    } else if (mode == 1) {          // 16-bit elements
        const uint4* p = (const uint4*)((const unsigned short*)mask_raw + (size_t)w * 32);
#pragma unroll
        for (int q = 0; q < 4; q++) {
            uint4 v = p[q];
            unsigned int words[4] = {v.x, v.y, v.z, v.w};
#pragma unroll
            for (int t = 0; t < 4; t++) {
                bits |= ((words[t] & 0x0000FFFFu) ? 1u : 0u) << (8 * q + 2 * t + 0);
                bits |= ((words[t] & 0xFFFF0000u) ? 1u : 0u) << (8 * q + 2 * t + 1);
            }
        }
    } else {                         // uint8 elements
        const uint4* p = (const uint4*)((const unsigned char*)mask_raw + (size_t)w * 32);
#pragma unroll
        for (int q = 0; q < 2; q++) {
            uint4 v = p[q];
            unsigned int words[4] = {v.x, v.y, v.z, v.w};
#pragma unroll
            for (int t = 0; t < 4; t++)
#pragma unroll
                for (int b = 0; b < 4; b++)
                    bits |= (((words[t] >> (8 * b)) & 0xffu) ? 1u : 0u) << (16 * q + 4 * t + b);
        }
    }
    g_mbits[w] = bits;
}

// ---------------------------------------------------------------------------
// 1) squared row norms (one warp per row)
// ---------------------------------------------------------------------------
__global__ __launch_bounds__(256) void norms_kernel(const float* __restrict__ emb) {
    int warp = (blockIdx.x * blockDim.x + threadIdx.x) >> 5;
    int lane = threadIdx.x & 31;
    if (warp >= TWO_N) return;
    const float4* p = (const float4*)(emb + (size_t)warp * DIMS);
    float s = 0.f;
#pragma unroll
    for (int c = 0; c < 2; c++) {
        float4 v = p[lane + 32 * c];
        s += v.x * v.x + v.y * v.y + v.z * v.z + v.w * v.w;
    }
#pragma unroll
    for (int o = 16; o > 0; o >>= 1) s += __shfl_down_sync(0xffffffffu, s, o);
    if (lane == 0) g_norms[warp] = s;
}

// ---------------------------------------------------------------------------
// 2) upper-triangular fused Gram + distance + masked exp, symmetric reuse.
//    2080 blocks, 256 threads, 8x8 outputs/thread, f32x2 packed FMA.
//    Thread (ty,tx): rows ty*8..+7; cols {tx*4..+3} and {64+tx*4..+3}
//    (split column groups -> conflict-free 16B-stride LDS.128 on B).
// ---------------------------------------------------------------------------
__global__ __launch_bounds__(256, 2) void pair_kernel(const float* __restrict__ emb) {
    __shared__ float As[BK][BMP];
    __shared__ float Bs[BK][BMP];
    __shared__ float rowpart[BM][17];
    __shared__ float colpart[BN][17];

    // decode linear tile id -> (by, bx) with bx >= by
    int t = blockIdx.x;
    int by = (int)((2 * NBLK + 1 - sqrtf((float)((2 * NBLK + 1) * (2 * NBLK + 1) - 8 * t))) * 0.5f);
    while ((by + 1) * NBLK - ((by + 1) * by) / 2 <= t) by++;    // fixup sqrt rounding
    while (by * NBLK - (by * (by - 1)) / 2 > t) by--;
    int bx = by + (t - (by * NBLK - (by * (by - 1)) / 2));
    const bool diag = (bx == by);

    const int tid = threadIdx.x;
    const int tx = tid & 15;
    const int ty = tid >> 4;
    const int rowBase = by * BM, colBase = bx * BN;

    unsigned long long acc[8][4];
#pragma unroll
    for (int i = 0; i < 8; i++)
#pragma unroll
        for (int j = 0; j < 4; j++) acc[i][j] = 0ull;

    for (int k0 = 0; k0 < DIMS; k0 += BK) {
#pragma unroll
        for (int c = 0; c < 4; c++) {
            int f4  = tid + c * 256;
            int row = f4 >> 3;
            int k4  = (f4 & 7) << 2;
            float4 va = *(const float4*)(emb + (size_t)(rowBase + row) * DIMS + k0 + k4);
            As[k4 + 0][row] = va.x; As[k4 + 1][row] = va.y;
            As[k4 + 2][row] = va.z; As[k4 + 3][row] = va.w;
            float4 vb = *(const float4*)(emb + (size_t)(colBase + row) * DIMS + k0 + k4);
            Bs[k4 + 0][row] = vb.x; Bs[k4 + 1][row] = vb.y;
            Bs[k4 + 2][row] = vb.z; Bs[k4 + 3][row] = vb.w;
        }
        __syncthreads();
#pragma unroll
        for (int kk = 0; kk < BK; kk++) {
            float4 a0 = *(const float4*)&As[kk][ty * 8];
            float4 a1 = *(const float4*)&As[kk][ty * 8 + 4];
            // conflict-free: lanes at 16B stride within each quarter-warp phase
            ulonglong2 bq0 = *(const ulonglong2*)&Bs[kk][tx * 4];
            ulonglong2 bq1 = *(const ulonglong2*)&Bs[kk][64 + tx * 4];
            unsigned long long bp[4] = {bq0.x, bq0.y, bq1.x, bq1.y};
            float av[8] = {a0.x, a0.y, a0.z, a0.w, a1.x, a1.y, a1.z, a1.w};
            unsigned long long a2[8];
#pragma unroll
            for (int i = 0; i < 8; i++)
                asm("mov.b64 %0, {%1, %1};" : "=l"(a2[i]) : "r"(__float_as_int(av[i])));
#pragma unroll
            for (int i = 0; i < 8; i++)
#pragma unroll
                for (int j = 0; j < 4; j++)
                    asm("fma.rn.f32x2 %0, %1, %2, %0;"
                        : "+l"(acc[i][j]) : "l"(a2[i]), "l"(bp[j]));
        }
        __syncthreads();
    }

    // ---- epilogue ----
    // thread's 8 columns: j<4 -> colBase + tx*4 + j ; j>=4 -> colBase + 64 + tx*4 + (j-4)
    float4 nc0 = *(const float4*)(g_norms + colBase + tx * 4);
    float4 nc1 = *(const float4*)(g_norms + colBase + 64 + tx * 4);
    float ncol[8] = {nc0.x, nc0.y, nc0.z, nc0.w, nc1.x, nc1.y, nc1.z, nc1.w};
    const unsigned char* mb8 = (const unsigned char*)g_mbits;
    const int colByte = colBase >> 3;
    const int nib = (tx & 1) * 4;

    // transposed mask bytes: mask[c][rowBase+ty*8 .. +7] for my 8 columns c
    unsigned int mbt[8];
#pragma unroll
    for (int j = 0; j < 8; j++) {
        int c = colBase + ((j < 4) ? (tx * 4 + j) : (64 + tx * 4 + j - 4));
        mbt[j] = diag ? 0u : mb8[(size_t)c * 1024 + (rowBase >> 3) + ty];
    }

    float strans[8] = {0.f, 0.f, 0.f, 0.f, 0.f, 0.f, 0.f, 0.f};
#pragma unroll
    for (int i = 0; i < 8; i++) {
        int r = rowBase + ty * 8 + i;
        float nr = __ldg(g_norms + r);
        // direct mask bits: nibble for cols tx*4..+3 and 64+tx*4..+3
        unsigned int n0 = (mb8[(size_t)r * 1024 + colByte + (tx >> 1)] >> nib) & 0xFu;
        unsigned int n1 = (mb8[(size_t)r * 1024 + colByte + 8 + (tx >> 1)] >> nib) & 0xFu;
        unsigned int mb = n0 | (n1 << 4);
        const float* dots = (const float*)acc[i];
        float s = 0.f;
#pragma unroll
        for (int j = 0; j < 8; j++) {
            float sq = nr + ncol[j] - 2.f * dots[j];
            sq = fmaxf(sq, 0.f);
            float d = sqrtf(sq + 1e-12f);
            int c = colBase + ((j < 4) ? (tx * 4 + j) : (64 + tx * 4 + j - 4));
            if (c - r == NHALF) g_ap[r] = d;           // bx = by+32, always in triangle
            float e = __expf(0.5f - d);
            if ((mb >> j) & 1u) s += e;                 // direct: rowsum[r], col c
            if ((mbt[j] >> i) & 1u) strans[j] += e;     // mirror: rowsum[c], col r
        }
        rowpart[ty * 8 + i][tx] = s;
    }
#pragma unroll
    for (int j = 0; j < 8; j++) {
        int lc = (j < 4) ? (tx * 4 + j) : (64 + tx * 4 + j - 4);
        colpart[lc][ty] = strans[j];
    }
    __syncthreads();

    if (tid < BM) {
        float s = 0.f;
#pragma unroll
        for (int k = 0; k < 16; k++) s += rowpart[tid][k];
        g_partial[(size_t)bx * TWO_N + rowBase + tid] = s;       // slot (p=bx, rows of by)
        if (!diag) {
            float sc = 0.f;
#pragma unroll
            for (int k = 0; k < 16; k++) sc += colpart[tid][k];
            g_partial[(size_t)by * TWO_N + colBase + tid] = sc;  // slot (p=by, rows of bx)
        }
    }
}

// ---------------------------------------------------------------------------
// 3) reduce partial row sums over the 64 column blocks
// ---------------------------------------------------------------------------
__global__ __launch_bounds__(256) void rowsum_kernel() {
    int r = blockIdx.x * blockDim.x + threadIdx.x;
    if (r >= TWO_N) return;
    float s = 0.f;
#pragma unroll
    for (int b = 0; b < NBLK; b++) s += g_partial[(size_t)b * TWO_N + r];
    g_rows[r] = s;
}

// ---------------------------------------------------------------------------
// 4) final loss (single block; deterministic)
// ---------------------------------------------------------------------------
__global__ __launch_bounds__(1024) void loss_kernel(float* __restrict__ out) {
    __shared__ float ssum[32];
    __shared__ int scnt[32];
    float s = 0.f;
    int cnt = 0;
    for (int i = threadIdx.x; i < NHALF; i += 1024) {
        float jv = logf(g_rows[i] + g_rows[i + NHALF]) + g_ap[i];
        if (!isnan(jv)) {
            float mj = fmaxf(jv, 0.f);
            s += mj * mj;
            cnt++;
        }
    }
    int lane = threadIdx.x & 31, w = threadIdx.x >> 5;
#pragma unroll
    for (int o = 16; o > 0; o >>= 1) {
        s += __shfl_down_sync(0xffffffffu, s, o);
        cnt += __shfl_down_sync(0xffffffffu, cnt, o);
    }
    if (lane == 0) { ssum[w] = s; scnt[w] = cnt; }
    __syncthreads();
    if (w == 0) {
        s = ssum[lane];
        cnt = scnt[lane];
#pragma unroll
        for (int o = 16; o > 0; o >>= 1) {
            s += __shfl_down_sync(0xffffffffu, s, o);
            cnt += __shfl_down_sync(0xffffffffu, cnt, o);
        }
        if (lane == 0) out[0] = s / fmaxf((float)cnt, 1.f) * 0.5f;
    }
}

// ---------------------------------------------------------------------------
extern "C" void kernel_launch(void* const* d_in, const int* in_sizes, int n_in,
                              void* d_out, int out_size) {
    const float* emb = (const float*)d_in[0];
    const void* mask = d_in[1];
    float* out = (float*)d_out;

    detect_kernel<<<1, 256>>>((const unsigned int*)mask);
    pack_kernel<<<TWO_N * 256 / 256, 256>>>(mask);
    norms_kernel<<<TWO_N / 8, 256>>>(emb);
    pair_kernel<<<NTILES, 256>>>(emb);
    rowsum_kernel<<<TWO_N / 256, 256>>>();
    loss_kernel<<<1, 1024>>>(out);
}